// round 14
// baseline (speedup 1.0000x reference)
#include <cuda_runtime.h>
#include <cuda_fp16.h>
#include <stdint.h>

// ---------------------------------------------------------------------------
// Dims: T=4096, IC=OC=4096, NOUT=204.
// Single-pass fp16 factorization:
//   wq[o][k] = scale[o] * sign[o][k]  with sign in {-1,0,+1} (exact in fp16)
//   outlier columns replaced; correction D'[o][j] = (ow - sign*scale)/s_eff
// A layout [T,  K]: [ x_f16(IC)   | x_gather_f16(NOUT) | pad0 ]
// B layout [OC, K]: [ sign_f16(IC)| D'_f16(NOUT)       | pad0 ]
// C[t][o] = (sum_k A[t][k]*B[o][k]) * s_eff[o] + bias[o]
// K = align64(IC + NOUT) = 4352. fp16 rel-err ~2e-4 << 1e-3 threshold.
// ---------------------------------------------------------------------------
#define MAX_OC 4096
#define MAX_IC 4096
#define MAXK   (MAX_IC + 256)   // 4352

__device__ __half g_A[(size_t)MAX_OC * MAXK];
__device__ __half g_B[(size_t)MAX_OC * MAXK];
__device__ float g_mean[MAX_OC];
__device__ float g_scale[MAX_OC];
__device__ float g_seff[MAX_OC];

// ---------------------------------------------------------------------------
// PTX helpers (sm_80-level: cp.async, ldmatrix, mma.sync)
// ---------------------------------------------------------------------------
__device__ __forceinline__ uint32_t smem_u32(const void* p) {
    uint32_t a;
    asm("{ .reg .u64 t; cvta.to.shared.u64 t, %1; cvt.u32.u64 %0, t; }"
        : "=r"(a) : "l"(p));
    return a;
}
#define CP_ASYNC16(dst, src) \
    asm volatile("cp.async.cg.shared.global [%0], [%1], 16;" :: "r"(dst), "l"(src))
#define CP_COMMIT() asm volatile("cp.async.commit_group;" ::: "memory")
#define CP_WAIT(n)  asm volatile("cp.async.wait_group %0;" :: "n"(n) : "memory")

__device__ __forceinline__ void ldsm4(uint32_t* r, uint32_t addr) {
    asm volatile("ldmatrix.sync.aligned.m8n8.x4.shared.b16 {%0,%1,%2,%3}, [%4];"
                 : "=r"(r[0]), "=r"(r[1]), "=r"(r[2]), "=r"(r[3]) : "r"(addr));
}
__device__ __forceinline__ void mma16816(float* d, const uint32_t* a,
                                         uint32_t b0, uint32_t b1) {
    asm volatile(
        "mma.sync.aligned.m16n8k16.row.col.f32.f16.f16.f32 "
        "{%0,%1,%2,%3}, {%4,%5,%6,%7}, {%8,%9}, {%0,%1,%2,%3};"
        : "+f"(d[0]), "+f"(d[1]), "+f"(d[2]), "+f"(d[3])
        : "r"(a[0]), "r"(a[1]), "r"(a[2]), "r"(a[3]), "r"(b0), "r"(b1));
}
__device__ __forceinline__ uint32_t swz(uint32_t off) {
    return off ^ ((off >> 3) & 0x70);
}

// ---------------------------------------------------------------------------
// Kernel 1 (fused): per-row stats + sign-matrix write.
// One block per output row. Row staged in smem; w read ONCE.
// ---------------------------------------------------------------------------
__global__ __launch_bounds__(256)
void prepB_fused(const float* __restrict__ w, int IC, int ktot) {
    __shared__ float srow[MAX_IC];
    __shared__ float red[256];
    int o = blockIdx.x;
    int tid = threadIdx.x;
    const float4* row4 = reinterpret_cast<const float4*>(w + (size_t)o * IC);
    float4* srow4 = reinterpret_cast<float4*>(srow);
    int n4 = IC / 4;   // 1024

    // Load row into smem, accumulate sum on the fly.
    float s = 0.f;
    for (int i = tid; i < n4; i += 256) {
        float4 v = row4[i];
        srow4[i] = v;
        s += v.x + v.y + v.z + v.w;
    }
    red[tid] = s;
    __syncthreads();
    #pragma unroll
    for (int off = 128; off > 0; off >>= 1) {
        if (tid < off) red[tid] += red[tid + off];
        __syncthreads();
    }
    float mean = red[0] / (float)IC;
    __syncthreads();

    // Mean absolute deviation from smem.
    float s2 = 0.f;
    for (int i = tid; i < IC; i += 256) s2 += fabsf(srow[i] - mean);
    red[tid] = s2;
    __syncthreads();
    #pragma unroll
    for (int off = 128; off > 0; off >>= 1) {
        if (tid < off) red[tid] += red[tid + off];
        __syncthreads();
    }
    float sc = red[0] / (float)IC;
    if (tid == 0) {
        g_mean[o]  = mean;
        g_scale[o] = sc;
        g_seff[o]  = fmaxf(sc, 1e-20f);
    }

    // Write sign row (fp16, exact) from smem.
    __half* rowp = g_B + (size_t)o * ktot;
    for (int i = tid; i < n4; i += 256) {
        float4 v = srow4[i];
        __half sg[4];
        float a;
        a = v.x - mean; sg[0] = __float2half_rn((a > 0.f) ? 1.f : ((a < 0.f) ? -1.f : 0.f));
        a = v.y - mean; sg[1] = __float2half_rn((a > 0.f) ? 1.f : ((a < 0.f) ? -1.f : 0.f));
        a = v.z - mean; sg[2] = __float2half_rn((a > 0.f) ? 1.f : ((a < 0.f) ? -1.f : 0.f));
        a = v.w - mean; sg[3] = __float2half_rn((a > 0.f) ? 1.f : ((a < 0.f) ? -1.f : 0.f));
        *reinterpret_cast<uint2*>(rowp + i * 4) = *reinterpret_cast<uint2*>(sg);
    }
}

// ---------------------------------------------------------------------------
// Kernel 2: B tail at offset IC: D' = (ow - sign*scale)/s_eff, then pad0.
// grid (1, OC), block = ntask (<=256).
// ---------------------------------------------------------------------------
__global__ void scatterB_kernel(const float* __restrict__ w,
                                const float* __restrict__ ow,
                                const int* __restrict__ cols,
                                int IC, int NOUT, int ktot) {
    int o = blockIdx.y;
    int j = threadIdx.x;
    int ntask = ktot - IC;
    if (j >= ntask) return;
    __half* rowp = g_B + (size_t)o * ktot + IC;
    if (j < NOUT) {
        int c = cols[j];
        float a = w[(size_t)o * IC + c] - g_mean[o];
        float sgn = (a > 0.f) ? 1.f : ((a < 0.f) ? -1.f : 0.f);
        float dp = (ow[(size_t)o * NOUT + j] - sgn * g_scale[o]) / g_seff[o];
        rowp[j] = __float2half_rn(dp);
    } else {
        rowp[j] = __float2half_rn(0.f);
    }
}

// ---------------------------------------------------------------------------
// Kernel 3: A main segment: x -> fp16. 2D grid, no div/mod, 2 float4/thread.
// grid (IC/2048, T), block 256.
// ---------------------------------------------------------------------------
__global__ void prepA_kernel(const float* __restrict__ x, int IC, int ktot) {
    int t  = blockIdx.y;
    int k4 = blockIdx.x * 512 + threadIdx.x;   // float4 index within row
    const float4* src = reinterpret_cast<const float4*>(x + (size_t)t * IC);
    __half* rowp = g_A + (size_t)t * ktot;
    #pragma unroll
    for (int u = 0; u < 2; u++) {
        int i = k4 + u * 256;
        float4 v = src[i];
        __half h[4];
        h[0] = __float2half_rn(v.x);
        h[1] = __float2half_rn(v.y);
        h[2] = __float2half_rn(v.z);
        h[3] = __float2half_rn(v.w);
        *reinterpret_cast<uint2*>(rowp + i * 4) = *reinterpret_cast<uint2*>(h);
    }
}

// ---------------------------------------------------------------------------
// Kernel 4: A tail at offset IC: gathered outlier x columns fp16 + pad0.
// grid (1, T), block = ntask (<=256).
// ---------------------------------------------------------------------------
__global__ void gatherA_kernel(const float* __restrict__ x,
                               const int* __restrict__ cols,
                               int IC, int NOUT, int ktot) {
    int t = blockIdx.y;
    int j = threadIdx.x;
    int ntask = ktot - IC;
    if (j >= ntask) return;
    __half* rowp = g_A + (size_t)t * ktot + IC;
    if (j < NOUT) {
        int c = cols[j];
        rowp[j] = __float2half_rn(x[(size_t)t * IC + c]);
    } else {
        rowp[j] = __float2half_rn(0.f);
    }
}

// ---------------------------------------------------------------------------
// Kernel 5: fp16 GEMM. BM=BN=128, BK=64, 8 warps (2m x 4n of 64x32 tiles),
// 3-stage cp.async pipeline, 2 CTAs/SM, ks-level register double-buffered
// fragments, epilogue scale+bias.  (UNCHANGED from R13)
// ---------------------------------------------------------------------------
#define BM 128
#define BN 128
#define BK 64
#define NSTAGE 3
#define TILE_BYTES   (128 * 128)                    // 16 KB per 128x64 f16 tile
#define STAGE_BYTES  (2 * TILE_BYTES)               // A + B = 32 KB
#define GEMM_SMEM    (NSTAGE * STAGE_BYTES + 1024)  // 97 KB -> 2 CTAs/SM

__device__ __forceinline__ void load_tile(uint32_t dst, const char* src,
                                          int tid, size_t rowbytes) {
    #pragma unroll
    for (int i = 0; i < 4; i++) {
        int idx = tid + i * 256;
        int r = idx >> 3, c = idx & 7;
        CP_ASYNC16(dst + swz((uint32_t)(r * 128 + c * 16)),
                   src + (size_t)r * rowbytes + c * 16);
    }
}

__global__ __launch_bounds__(256, 2)
void gemm_mma(const float* __restrict__ bias, float* __restrict__ C,
              int T, int OC, int ktot) {
    extern __shared__ char sm_raw[];
    uint32_t raw = smem_u32(sm_raw);
    uint32_t sbase = (raw + 1023u) & ~1023u;

    const int tid = threadIdx.x;
    const int lane = tid & 31, wid = tid >> 5;
    const int wm = (wid & 1) * 64;       // 2 warps in m
    const int wn = (wid >> 1) * 32;      // 4 warps in n

    const char* Ag = reinterpret_cast<const char*>(g_A + (size_t)(blockIdx.y * BM) * ktot);
    const char* Bg = reinterpret_cast<const char*>(g_B + (size_t)(blockIdx.x * BN) * ktot);
    const size_t rowbytes = (size_t)ktot * 2;

    float acc[4][4][4];
    #pragma unroll
    for (int mi = 0; mi < 4; mi++)
        #pragma unroll
        for (int nb = 0; nb < 4; nb++)
            #pragma unroll
            for (int e = 0; e < 4; e++) acc[mi][nb][e] = 0.f;

    const int nch = ktot / BK;

    #pragma unroll
    for (int s = 0; s < NSTAGE - 1; s++) {
        uint32_t st = sbase + (uint32_t)s * STAGE_BYTES;
        load_tile(st,              Ag + (size_t)s * 128, tid, rowbytes);
        load_tile(st + TILE_BYTES, Bg + (size_t)s * 128, tid, rowbytes);
        CP_COMMIT();
    }

    const int lrow = lane & 15;
    const int lkoff = (lane >> 4) * 16;
    const uint32_t arowoff = (uint32_t)((wm + lrow) * 128 + lkoff);
    const uint32_t browoff = (uint32_t)((wn + lrow) * 128 + lkoff);

    uint32_t afrag[2][4][4], bfrag[2][2][4];

    for (int ch = 0; ch < nch; ch++) {
        CP_WAIT(NSTAGE - 2);
        __syncthreads();

        int pf = ch + NSTAGE - 1;
        if (pf < nch) {
            uint32_t st = sbase + (uint32_t)(pf % NSTAGE) * STAGE_BYTES;
            load_tile(st,              Ag + (size_t)pf * 128, tid, rowbytes);
            load_tile(st + TILE_BYTES, Bg + (size_t)pf * 128, tid, rowbytes);
        }
        CP_COMMIT();

        uint32_t st = sbase + (uint32_t)(ch % NSTAGE) * STAGE_BYTES;
        uint32_t ab = st, bb = st + TILE_BYTES;

        // Preload ks=0 fragments into buffer 0.
        #pragma unroll
        for (int ni = 0; ni < 2; ni++)
            ldsm4(bfrag[0][ni], bb + swz(browoff + (uint32_t)(ni * 2048)));
        #pragma unroll
        for (int mi = 0; mi < 4; mi++)
            ldsm4(afrag[0][mi], ab + swz(arowoff + (uint32_t)(mi * 2048)));

        #pragma unroll
        for (int ks = 0; ks < 4; ks++) {
            int cur = ks & 1;
            int nxt = cur ^ 1;
            if (ks < 3) {
                uint32_t ko = (uint32_t)((ks + 1) * 32);
                #pragma unroll
                for (int ni = 0; ni < 2; ni++)
                    ldsm4(bfrag[nxt][ni],
                          bb + swz(browoff + ko + (uint32_t)(ni * 2048)));
                #pragma unroll
                for (int mi = 0; mi < 4; mi++)
                    ldsm4(afrag[nxt][mi],
                          ab + swz(arowoff + ko + (uint32_t)(mi * 2048)));
            }
            #pragma unroll
            for (int mi = 0; mi < 4; mi++) {
                #pragma unroll
                for (int ni = 0; ni < 2; ni++) {
                    mma16816(acc[mi][2 * ni],     afrag[cur][mi],
                             bfrag[cur][ni][0], bfrag[cur][ni][2]);
                    mma16816(acc[mi][2 * ni + 1], afrag[cur][mi],
                             bfrag[cur][ni][1], bfrag[cur][ni][3]);
                }
            }
        }
    }

    // Epilogue: C = acc * s_eff[col] + bias[col]
    int colb = blockIdx.x * BN + wn + (lane & 3) * 2;
    int rowb = blockIdx.y * BM + wm + (lane >> 2);
    #pragma unroll
    for (int nb = 0; nb < 4; nb++) {
        int col = colb + nb * 8;
        float s0 = g_seff[col],     s1 = g_seff[col + 1];
        float b0 = bias[col],       b1 = bias[col + 1];
        #pragma unroll
        for (int mi = 0; mi < 4; mi++) {
            int row = rowb + mi * 16;
            float2 v0 = make_float2(acc[mi][nb][0] * s0 + b0,
                                    acc[mi][nb][1] * s1 + b1);
            float2 v1 = make_float2(acc[mi][nb][2] * s0 + b0,
                                    acc[mi][nb][3] * s1 + b1);
            *reinterpret_cast<float2*>(C + (size_t)row * OC + col)       = v0;
            *reinterpret_cast<float2*>(C + (size_t)(row + 8) * OC + col) = v1;
        }
    }
}

// ---------------------------------------------------------------------------
// Launch
// ---------------------------------------------------------------------------
extern "C" void kernel_launch(void* const* d_in, const int* in_sizes, int n_in,
                              void* d_out, int out_size) {
    const float* x    = (const float*)d_in[0];
    const float* w    = (const float*)d_in[1];
    const float* bias = (const float*)d_in[2];
    const float* ow   = (const float*)d_in[3];
    const int*   cols = (const int*)d_in[4];

    int OC   = in_sizes[2];
    int IC   = in_sizes[1] / OC;
    int T    = in_sizes[0] / IC;
    int NOUT = in_sizes[3] / OC;
    int ktot = (IC + NOUT + 63) & ~63;   // 4352
    int ntask = ktot - IC;               // 256

    float* out = (float*)d_out;

    // 1) fused row stats + sign write (single pass over w)
    prepB_fused<<<OC, 256>>>(w, IC, ktot);

    // 2) B outlier tail
    {
        dim3 grid(1, OC);
        scatterB_kernel<<<grid, ntask>>>(w, ow, cols, IC, NOUT, ktot);
    }
    // 3) A main segment
    {
        dim3 grid(IC / 2048, T);
        prepA_kernel<<<grid, 256>>>(x, IC, ktot);
    }
    // 4) A outlier tail
    {
        dim3 grid(1, T);
        gatherA_kernel<<<grid, ntask>>>(x, cols, IC, NOUT, ktot);
    }
    // 5) GEMM + scaled epilogue
    {
        static bool attr_set = false;
        if (!attr_set) {
            cudaFuncSetAttribute(gemm_mma,
                                 cudaFuncAttributeMaxDynamicSharedMemorySize,
                                 GEMM_SMEM);
            attr_set = true;
        }
        dim3 grid(OC / BN, T / BM);
        gemm_mma<<<grid, 256, GEMM_SMEM>>>(bias, out, T, OC, ktot);
    }
}

// round 15
// speedup vs baseline: 1.5249x; 1.5249x over previous
#include <cuda_runtime.h>
#include <cuda_fp16.h>
#include <stdint.h>

// ---------------------------------------------------------------------------
// Dims: T=4096, IC=OC=4096, NOUT=204.
// Single-pass fp16 factorization:
//   wq[o][k] = scale[o] * sign[o][k]  with sign in {-1,0,+1} (exact in fp16)
//   outlier columns replaced; correction D'[o][j] = (ow - sign*scale)/s_eff
// A layout [T,  K]: [ x_f16(IC)   | x_gather_f16(NOUT) | pad0 ]
// B layout [OC, K]: [ sign_f16(IC)| D'_f16(NOUT)       | pad0 ]
// C[t][o] = (sum_k A[t][k]*B[o][k]) * s_eff[o] + bias[o]
// K = align64(IC + NOUT) = 4352. fp16 rel-err ~2e-4 << 1e-3 threshold.
// ---------------------------------------------------------------------------
#define MAX_OC 4096
#define MAX_IC 4096
#define MAXK   (MAX_IC + 256)   // 4352

__device__ __half g_A[(size_t)MAX_OC * MAXK];
__device__ __half g_B[(size_t)MAX_OC * MAXK];
__device__ float g_mean[MAX_OC];
__device__ float g_scale[MAX_OC];
__device__ float g_seff[MAX_OC];

// ---------------------------------------------------------------------------
// PTX helpers (sm_80-level: cp.async, ldmatrix, mma.sync)
// ---------------------------------------------------------------------------
__device__ __forceinline__ uint32_t smem_u32(const void* p) {
    uint32_t a;
    asm("{ .reg .u64 t; cvta.to.shared.u64 t, %1; cvt.u32.u64 %0, t; }"
        : "=r"(a) : "l"(p));
    return a;
}
#define CP_ASYNC16(dst, src) \
    asm volatile("cp.async.cg.shared.global [%0], [%1], 16;" :: "r"(dst), "l"(src))
#define CP_COMMIT() asm volatile("cp.async.commit_group;" ::: "memory")
#define CP_WAIT(n)  asm volatile("cp.async.wait_group %0;" :: "n"(n) : "memory")

__device__ __forceinline__ void ldsm4(uint32_t* r, uint32_t addr) {
    asm volatile("ldmatrix.sync.aligned.m8n8.x4.shared.b16 {%0,%1,%2,%3}, [%4];"
                 : "=r"(r[0]), "=r"(r[1]), "=r"(r[2]), "=r"(r[3]) : "r"(addr));
}
__device__ __forceinline__ void mma16816(float* d, const uint32_t* a,
                                         uint32_t b0, uint32_t b1) {
    asm volatile(
        "mma.sync.aligned.m16n8k16.row.col.f32.f16.f16.f32 "
        "{%0,%1,%2,%3}, {%4,%5,%6,%7}, {%8,%9}, {%0,%1,%2,%3};"
        : "+f"(d[0]), "+f"(d[1]), "+f"(d[2]), "+f"(d[3])
        : "r"(a[0]), "r"(a[1]), "r"(a[2]), "r"(a[3]), "r"(b0), "r"(b1));
}
__device__ __forceinline__ uint32_t swz(uint32_t off) {
    return off ^ ((off >> 3) & 0x70);
}

// Block-wide sum reduction (256 threads) via shuffles + one smem hop.
__device__ __forceinline__ float block_sum256(float v, float* sred) {
    #pragma unroll
    for (int off = 16; off > 0; off >>= 1)
        v += __shfl_xor_sync(0xFFFFFFFFu, v, off);
    int lane = threadIdx.x & 31, warp = threadIdx.x >> 5;
    if (lane == 0) sred[warp] = v;
    __syncthreads();
    float r = (threadIdx.x < 8) ? sred[threadIdx.x] : 0.f;
    if (threadIdx.x < 32) {
        #pragma unroll
        for (int off = 4; off > 0; off >>= 1)
            r += __shfl_xor_sync(0xFFFFFFFFu, r, off);
        if (threadIdx.x == 0) sred[8] = r;
    }
    __syncthreads();
    return sred[8];
}

// ---------------------------------------------------------------------------
// Kernel 1: per-output-row mean / mean-abs-dev (float4 + shuffle reduce).
// ---------------------------------------------------------------------------
__global__ __launch_bounds__(256)
void rowstats_kernel(const float* __restrict__ w, int IC) {
    __shared__ float sred[9];
    int o = blockIdx.x;
    int tid = threadIdx.x;
    const float4* row4 = reinterpret_cast<const float4*>(w + (size_t)o * IC);
    int n4 = IC / 4;

    float s = 0.f;
    for (int i = tid; i < n4; i += 256) {
        float4 v = row4[i];
        s += (v.x + v.y) + (v.z + v.w);
    }
    float mean = block_sum256(s, sred) / (float)IC;
    __syncthreads();

    float s2 = 0.f;
    for (int i = tid; i < n4; i += 256) {
        float4 v = row4[i];
        s2 += fabsf(v.x - mean) + fabsf(v.y - mean)
            + fabsf(v.z - mean) + fabsf(v.w - mean);
    }
    float sc = block_sum256(s2, sred) / (float)IC;
    if (tid == 0) {
        g_mean[o]  = mean;
        g_scale[o] = sc;
        g_seff[o]  = fmaxf(sc, 1e-20f);
    }
}

// ---------------------------------------------------------------------------
// Kernel 2: B = sign matrix in fp16 (2D grid, no div/mod) + fused tail:
// blockIdx.x==0 also writes D' = (ow - sign*scale)/s_eff and pad0.
// grid (IC/1024, OC), block 256.
// ---------------------------------------------------------------------------
__global__ __launch_bounds__(256)
void prepB_kernel(const float* __restrict__ w,
                  const float* __restrict__ ow,
                  const int* __restrict__ cols,
                  int IC, int NOUT, int ktot) {
    int o  = blockIdx.y;
    int k4 = blockIdx.x * 256 + threadIdx.x;   // float4 index within row
    float mean = g_mean[o];
    float4 v = reinterpret_cast<const float4*>(w + (size_t)o * IC)[k4];
    __half sg[4];
    float a;
    a = v.x - mean; sg[0] = __float2half_rn((a > 0.f) ? 1.f : ((a < 0.f) ? -1.f : 0.f));
    a = v.y - mean; sg[1] = __float2half_rn((a > 0.f) ? 1.f : ((a < 0.f) ? -1.f : 0.f));
    a = v.z - mean; sg[2] = __float2half_rn((a > 0.f) ? 1.f : ((a < 0.f) ? -1.f : 0.f));
    a = v.w - mean; sg[3] = __float2half_rn((a > 0.f) ? 1.f : ((a < 0.f) ? -1.f : 0.f));
    *reinterpret_cast<uint2*>(g_B + (size_t)o * ktot + k4 * 4) =
        *reinterpret_cast<uint2*>(sg);

    // Fused outlier tail (one block-column handles all ntask elements).
    if (blockIdx.x == 0) {
        int j = threadIdx.x;
        int ntask = ktot - IC;
        if (j < ntask) {
            __half* rowp = g_B + (size_t)o * ktot + IC;
            if (j < NOUT) {
                int c = cols[j];
                float aw = w[(size_t)o * IC + c] - mean;
                float sgn = (aw > 0.f) ? 1.f : ((aw < 0.f) ? -1.f : 0.f);
                float dp = (ow[(size_t)o * NOUT + j] - sgn * g_scale[o]) / g_seff[o];
                rowp[j] = __float2half_rn(dp);
            } else {
                rowp[j] = __float2half_rn(0.f);
            }
        }
    }
}

// ---------------------------------------------------------------------------
// Kernel 3: A = x in fp16 (2D grid, no div/mod) + fused tail gather:
// blockIdx.x==0 also writes gathered outlier columns + pad0.
// grid (IC/1024, T), block 256.
// ---------------------------------------------------------------------------
__global__ __launch_bounds__(256)
void prepA_kernel(const float* __restrict__ x,
                  const int* __restrict__ cols,
                  int IC, int NOUT, int ktot) {
    int t  = blockIdx.y;
    int k4 = blockIdx.x * 256 + threadIdx.x;
    float4 v = reinterpret_cast<const float4*>(x + (size_t)t * IC)[k4];
    __half h[4];
    h[0] = __float2half_rn(v.x);
    h[1] = __float2half_rn(v.y);
    h[2] = __float2half_rn(v.z);
    h[3] = __float2half_rn(v.w);
    *reinterpret_cast<uint2*>(g_A + (size_t)t * ktot + k4 * 4) =
        *reinterpret_cast<uint2*>(h);

    if (blockIdx.x == 0) {
        int j = threadIdx.x;
        int ntask = ktot - IC;
        if (j < ntask) {
            __half* rowp = g_A + (size_t)t * ktot + IC;
            if (j < NOUT) {
                int c = cols[j];
                rowp[j] = __float2half_rn(x[(size_t)t * IC + c]);
            } else {
                rowp[j] = __float2half_rn(0.f);
            }
        }
    }
}

// ---------------------------------------------------------------------------
// Kernel 4: fp16 GEMM. BM=BN=128, BK=64, 8 warps (2m x 4n of 64x32 tiles),
// 3-stage cp.async pipeline, 2 CTAs/SM, ks-level register double-buffered
// fragments, epilogue scale+bias.  (UNCHANGED from R13)
// ---------------------------------------------------------------------------
#define BM 128
#define BN 128
#define BK 64
#define NSTAGE 3
#define TILE_BYTES   (128 * 128)                    // 16 KB per 128x64 f16 tile
#define STAGE_BYTES  (2 * TILE_BYTES)               // A + B = 32 KB
#define GEMM_SMEM    (NSTAGE * STAGE_BYTES + 1024)  // 97 KB -> 2 CTAs/SM

__device__ __forceinline__ void load_tile(uint32_t dst, const char* src,
                                          int tid, size_t rowbytes) {
    #pragma unroll
    for (int i = 0; i < 4; i++) {
        int idx = tid + i * 256;
        int r = idx >> 3, c = idx & 7;
        CP_ASYNC16(dst + swz((uint32_t)(r * 128 + c * 16)),
                   src + (size_t)r * rowbytes + c * 16);
    }
}

__global__ __launch_bounds__(256, 2)
void gemm_mma(const float* __restrict__ bias, float* __restrict__ C,
              int T, int OC, int ktot) {
    extern __shared__ char sm_raw[];
    uint32_t raw = smem_u32(sm_raw);
    uint32_t sbase = (raw + 1023u) & ~1023u;

    const int tid = threadIdx.x;
    const int lane = tid & 31, wid = tid >> 5;
    const int wm = (wid & 1) * 64;       // 2 warps in m
    const int wn = (wid >> 1) * 32;      // 4 warps in n

    const char* Ag = reinterpret_cast<const char*>(g_A + (size_t)(blockIdx.y * BM) * ktot);
    const char* Bg = reinterpret_cast<const char*>(g_B + (size_t)(blockIdx.x * BN) * ktot);
    const size_t rowbytes = (size_t)ktot * 2;

    float acc[4][4][4];
    #pragma unroll
    for (int mi = 0; mi < 4; mi++)
        #pragma unroll
        for (int nb = 0; nb < 4; nb++)
            #pragma unroll
            for (int e = 0; e < 4; e++) acc[mi][nb][e] = 0.f;

    const int nch = ktot / BK;

    #pragma unroll
    for (int s = 0; s < NSTAGE - 1; s++) {
        uint32_t st = sbase + (uint32_t)s * STAGE_BYTES;
        load_tile(st,              Ag + (size_t)s * 128, tid, rowbytes);
        load_tile(st + TILE_BYTES, Bg + (size_t)s * 128, tid, rowbytes);
        CP_COMMIT();
    }

    const int lrow = lane & 15;
    const int lkoff = (lane >> 4) * 16;
    const uint32_t arowoff = (uint32_t)((wm + lrow) * 128 + lkoff);
    const uint32_t browoff = (uint32_t)((wn + lrow) * 128 + lkoff);

    uint32_t afrag[2][4][4], bfrag[2][2][4];

    for (int ch = 0; ch < nch; ch++) {
        CP_WAIT(NSTAGE - 2);
        __syncthreads();

        int pf = ch + NSTAGE - 1;
        if (pf < nch) {
            uint32_t st = sbase + (uint32_t)(pf % NSTAGE) * STAGE_BYTES;
            load_tile(st,              Ag + (size_t)pf * 128, tid, rowbytes);
            load_tile(st + TILE_BYTES, Bg + (size_t)pf * 128, tid, rowbytes);
        }
        CP_COMMIT();

        uint32_t st = sbase + (uint32_t)(ch % NSTAGE) * STAGE_BYTES;
        uint32_t ab = st, bb = st + TILE_BYTES;

        // Preload ks=0 fragments into buffer 0.
        #pragma unroll
        for (int ni = 0; ni < 2; ni++)
            ldsm4(bfrag[0][ni], bb + swz(browoff + (uint32_t)(ni * 2048)));
        #pragma unroll
        for (int mi = 0; mi < 4; mi++)
            ldsm4(afrag[0][mi], ab + swz(arowoff + (uint32_t)(mi * 2048)));

        #pragma unroll
        for (int ks = 0; ks < 4; ks++) {
            int cur = ks & 1;
            int nxt = cur ^ 1;
            if (ks < 3) {
                uint32_t ko = (uint32_t)((ks + 1) * 32);
                #pragma unroll
                for (int ni = 0; ni < 2; ni++)
                    ldsm4(bfrag[nxt][ni],
                          bb + swz(browoff + ko + (uint32_t)(ni * 2048)));
                #pragma unroll
                for (int mi = 0; mi < 4; mi++)
                    ldsm4(afrag[nxt][mi],
                          ab + swz(arowoff + ko + (uint32_t)(mi * 2048)));
            }
            #pragma unroll
            for (int mi = 0; mi < 4; mi++) {
                #pragma unroll
                for (int ni = 0; ni < 2; ni++) {
                    mma16816(acc[mi][2 * ni],     afrag[cur][mi],
                             bfrag[cur][ni][0], bfrag[cur][ni][2]);
                    mma16816(acc[mi][2 * ni + 1], afrag[cur][mi],
                             bfrag[cur][ni][1], bfrag[cur][ni][3]);
                }
            }
        }
    }

    // Epilogue: C = acc * s_eff[col] + bias[col]
    int colb = blockIdx.x * BN + wn + (lane & 3) * 2;
    int rowb = blockIdx.y * BM + wm + (lane >> 2);
    #pragma unroll
    for (int nb = 0; nb < 4; nb++) {
        int col = colb + nb * 8;
        float s0 = g_seff[col],     s1 = g_seff[col + 1];
        float b0 = bias[col],       b1 = bias[col + 1];
        #pragma unroll
        for (int mi = 0; mi < 4; mi++) {
            int row = rowb + mi * 16;
            float2 v0 = make_float2(acc[mi][nb][0] * s0 + b0,
                                    acc[mi][nb][1] * s1 + b1);
            float2 v1 = make_float2(acc[mi][nb][2] * s0 + b0,
                                    acc[mi][nb][3] * s1 + b1);
            *reinterpret_cast<float2*>(C + (size_t)row * OC + col)       = v0;
            *reinterpret_cast<float2*>(C + (size_t)(row + 8) * OC + col) = v1;
        }
    }
}

// ---------------------------------------------------------------------------
// Launch
// ---------------------------------------------------------------------------
extern "C" void kernel_launch(void* const* d_in, const int* in_sizes, int n_in,
                              void* d_out, int out_size) {
    const float* x    = (const float*)d_in[0];
    const float* w    = (const float*)d_in[1];
    const float* bias = (const float*)d_in[2];
    const float* ow   = (const float*)d_in[3];
    const int*   cols = (const int*)d_in[4];

    int OC   = in_sizes[2];
    int IC   = in_sizes[1] / OC;
    int T    = in_sizes[0] / IC;
    int NOUT = in_sizes[3] / OC;
    int ktot = (IC + NOUT + 63) & ~63;   // 4352

    float* out = (float*)d_out;

    // 1) row stats
    rowstats_kernel<<<OC, 256>>>(w, IC);

    // 2) B sign matrix + fused outlier tail
    {
        dim3 grid(IC / 1024, OC);
        prepB_kernel<<<grid, 256>>>(w, ow, cols, IC, NOUT, ktot);
    }
    // 3) A fp16 + fused gathered tail
    {
        dim3 grid(IC / 1024, T);
        prepA_kernel<<<grid, 256>>>(x, cols, IC, NOUT, ktot);
    }
    // 4) GEMM + scaled epilogue
    {
        static bool attr_set = false;
        if (!attr_set) {
            cudaFuncSetAttribute(gemm_mma,
                                 cudaFuncAttributeMaxDynamicSharedMemorySize,
                                 GEMM_SMEM);
            attr_set = true;
        }
        dim3 grid(OC / BN, T / BM);
        gemm_mma<<<grid, 256, GEMM_SMEM>>>(bias, out, T, OC, ktot);
    }
}

// round 16
// speedup vs baseline: 1.6913x; 1.1091x over previous
#include <cuda_runtime.h>
#include <cuda_fp16.h>
#include <stdint.h>

// ---------------------------------------------------------------------------
// Dims: T=4096, IC=OC=4096, NOUT=204.  K = align64(IC+NOUT) = 4352.
// Single-pass fp16 factorization:
//   wq[o][k] = scale[o]*sign[o][k], sign in {-1,0,+1} exact in fp16;
//   outlier cols replaced via D'[o][j] = (ow - sign*scale)/s_eff appended to K.
// C[t][o] = (sum_k A[t][k]*B[o][k]) * s_eff[o] + bias[o]
//
// NEW (R16): A and B are stored TILE-CONTIGUOUS and PRE-SWIZZLED:
//   tile(bm, ch) = 128 rows x 64 k (16 KB), at byte offset (bm*NCH+ch)*16384,
//   element (r, c) at swz(r*128 + c*2) within the tile.
// GEMM stage loads are 2x cp.async.bulk (16 KB each) + mbarrier expect_tx.
// ---------------------------------------------------------------------------
#define MAX_OC 4096
#define MAX_IC 4096
#define MAXK   (MAX_IC + 256)   // 4352
#define NCH    (MAXK / 64)      // 68 chunks
#define TILE_BYTES 16384        // 128 rows x 128 bytes

__device__ __align__(1024) __half g_A[(size_t)MAX_OC * MAXK];
__device__ __align__(1024) __half g_B[(size_t)MAX_OC * MAXK];
__device__ float g_mean[MAX_OC];
__device__ float g_scale[MAX_OC];
__device__ float g_seff[MAX_OC];

// ---------------------------------------------------------------------------
// PTX helpers
// ---------------------------------------------------------------------------
__device__ __forceinline__ uint32_t smem_u32(const void* p) {
    uint32_t a;
    asm("{ .reg .u64 t; cvta.to.shared.u64 t, %1; cvt.u32.u64 %0, t; }"
        : "=r"(a) : "l"(p));
    return a;
}
#define MBAR_INIT(addr, cnt) \
    asm volatile("mbarrier.init.shared.b64 [%0], %1;" :: "r"(addr), "r"(cnt) : "memory")
#define MBAR_EXPECT_TX(addr, bytes) \
    asm volatile("mbarrier.arrive.expect_tx.shared.b64 _, [%0], %1;" \
                 :: "r"(addr), "r"(bytes) : "memory")
#define MBAR_WAIT(addr, parity) do {                                          \
    uint32_t _m = (addr), _p = (parity), _d;                                  \
    asm volatile("{\n\t.reg .pred p;\n\t"                                     \
        "mbarrier.try_wait.parity.acquire.cta.shared::cta.b64 p, [%1], %2;\n\t" \
        "selp.b32 %0, 1, 0, p;\n\t}" : "=r"(_d) : "r"(_m), "r"(_p) : "memory"); \
    if (!_d) {                                                                \
        asm volatile("{\n\t.reg .pred P1;\n\t"                                \
            "WL_%=:\n\t"                                                      \
            "mbarrier.try_wait.parity.acquire.cta.shared::cta.b64 P1, [%0], %1, 0x989680;\n\t" \
            "@P1 bra.uni WD_%=;\n\t"                                          \
            "bra.uni WL_%=;\n\t"                                              \
            "WD_%=:\n\t}" :: "r"(_m), "r"(_p) : "memory");                    \
    }                                                                         \
} while (0)
#define BULK_CP(dst, src, bytes, mbar) \
    asm volatile("cp.async.bulk.shared::cluster.global.mbarrier::complete_tx::bytes " \
                 "[%0], [%1], %2, [%3];" \
                 :: "r"(dst), "l"(src), "r"(bytes), "r"(mbar) : "memory")
#define FENCE_ASYNC_SHARED() \
    asm volatile("fence.proxy.async.shared::cta;" ::: "memory")

__device__ __forceinline__ void ldsm4(uint32_t* r, uint32_t addr) {
    asm volatile("ldmatrix.sync.aligned.m8n8.x4.shared.b16 {%0,%1,%2,%3}, [%4];"
                 : "=r"(r[0]), "=r"(r[1]), "=r"(r[2]), "=r"(r[3]) : "r"(addr));
}
__device__ __forceinline__ void mma16816(float* d, const uint32_t* a,
                                         uint32_t b0, uint32_t b1) {
    asm volatile(
        "mma.sync.aligned.m16n8k16.row.col.f32.f16.f16.f32 "
        "{%0,%1,%2,%3}, {%4,%5,%6,%7}, {%8,%9}, {%0,%1,%2,%3};"
        : "+f"(d[0]), "+f"(d[1]), "+f"(d[2]), "+f"(d[3])
        : "r"(a[0]), "r"(a[1]), "r"(a[2]), "r"(a[3]), "r"(b0), "r"(b1));
}
__device__ __forceinline__ uint32_t swz(uint32_t off) {
    return off ^ ((off >> 3) & 0x70);
}

// Block-wide sum reduction (256 threads) via shuffles + one smem hop.
__device__ __forceinline__ float block_sum256(float v, float* sred) {
    #pragma unroll
    for (int off = 16; off > 0; off >>= 1)
        v += __shfl_xor_sync(0xFFFFFFFFu, v, off);
    int lane = threadIdx.x & 31, warp = threadIdx.x >> 5;
    if (lane == 0) sred[warp] = v;
    __syncthreads();
    float r = (threadIdx.x < 8) ? sred[threadIdx.x] : 0.f;
    if (threadIdx.x < 32) {
        #pragma unroll
        for (int off = 4; off > 0; off >>= 1)
            r += __shfl_xor_sync(0xFFFFFFFFu, r, off);
        if (threadIdx.x == 0) sred[8] = r;
    }
    __syncthreads();
    return sred[8];
}

// Tile-layout address: element (row_in_tile r, k) of matrix block bm.
__device__ __forceinline__ size_t tile_off(int bm, int r, int k, int nch) {
    int ch = k >> 6;
    uint32_t inner = (uint32_t)(r * 128 + (k & 63) * 2);
    return (size_t)(bm * nch + ch) * TILE_BYTES + swz(inner);
}

// ---------------------------------------------------------------------------
// Kernel 1: per-output-row mean / mean-abs-dev (float4 + shuffle reduce).
// ---------------------------------------------------------------------------
__global__ __launch_bounds__(256)
void rowstats_kernel(const float* __restrict__ w, int IC) {
    __shared__ float sred[9];
    int o = blockIdx.x;
    int tid = threadIdx.x;
    const float4* row4 = reinterpret_cast<const float4*>(w + (size_t)o * IC);
    int n4 = IC / 4;

    float s = 0.f;
    for (int i = tid; i < n4; i += 256) {
        float4 v = row4[i];
        s += (v.x + v.y) + (v.z + v.w);
    }
    float mean = block_sum256(s, sred) / (float)IC;
    __syncthreads();

    float s2 = 0.f;
    for (int i = tid; i < n4; i += 256) {
        float4 v = row4[i];
        s2 += fabsf(v.x - mean) + fabsf(v.y - mean)
            + fabsf(v.z - mean) + fabsf(v.w - mean);
    }
    float sc = block_sum256(s2, sred) / (float)IC;
    if (tid == 0) {
        g_mean[o]  = mean;
        g_scale[o] = sc;
        g_seff[o]  = fmaxf(sc, 1e-20f);
    }
}

// ---------------------------------------------------------------------------
// Kernel 2: B sign matrix -> tiled/swizzled layout + fused outlier tail.
// grid (IC/1024, OC), block 256; each thread one float4 (4 k-values, 8B out).
// ---------------------------------------------------------------------------
__global__ __launch_bounds__(256)
void prepB_kernel(const float* __restrict__ w,
                  const float* __restrict__ ow,
                  const int* __restrict__ cols,
                  int IC, int NOUT, int ktot) {
    int o  = blockIdx.y;
    int k4 = blockIdx.x * 256 + threadIdx.x;   // float4 index within row
    int nch = ktot >> 6;
    int bm = o >> 7, r = o & 127;
    float mean = g_mean[o];
    float4 v = reinterpret_cast<const float4*>(w + (size_t)o * IC)[k4];
    __half sg[4];
    float a;
    a = v.x - mean; sg[0] = __float2half_rn((a > 0.f) ? 1.f : ((a < 0.f) ? -1.f : 0.f));
    a = v.y - mean; sg[1] = __float2half_rn((a > 0.f) ? 1.f : ((a < 0.f) ? -1.f : 0.f));
    a = v.z - mean; sg[2] = __float2half_rn((a > 0.f) ? 1.f : ((a < 0.f) ? -1.f : 0.f));
    a = v.w - mean; sg[3] = __float2half_rn((a > 0.f) ? 1.f : ((a < 0.f) ? -1.f : 0.f));
    char* base = reinterpret_cast<char*>(g_B);
    *reinterpret_cast<uint2*>(base + tile_off(bm, r, k4 * 4, nch)) =
        *reinterpret_cast<uint2*>(sg);

    // Fused outlier tail (first block-column writes ntask k-positions).
    if (blockIdx.x == 0) {
        int j = threadIdx.x;
        int ntask = ktot - IC;
        if (j < ntask) {
            __half hv;
            if (j < NOUT) {
                int c = cols[j];
                float aw = w[(size_t)o * IC + c] - mean;
                float sgn = (aw > 0.f) ? 1.f : ((aw < 0.f) ? -1.f : 0.f);
                float dp = (ow[(size_t)o * NOUT + j] - sgn * g_scale[o]) / g_seff[o];
                hv = __float2half_rn(dp);
            } else {
                hv = __float2half_rn(0.f);
            }
            *reinterpret_cast<__half*>(base + tile_off(bm, r, IC + j, nch)) = hv;
        }
    }
}

// ---------------------------------------------------------------------------
// Kernel 3: A = x fp16 -> tiled/swizzled layout + fused gathered tail.
// grid (IC/1024, T), block 256.
// ---------------------------------------------------------------------------
__global__ __launch_bounds__(256)
void prepA_kernel(const float* __restrict__ x,
                  const int* __restrict__ cols,
                  int IC, int NOUT, int ktot) {
    int t  = blockIdx.y;
    int k4 = blockIdx.x * 256 + threadIdx.x;
    int nch = ktot >> 6;
    int bm = t >> 7, r = t & 127;
    float4 v = reinterpret_cast<const float4*>(x + (size_t)t * IC)[k4];
    __half h[4];
    h[0] = __float2half_rn(v.x);
    h[1] = __float2half_rn(v.y);
    h[2] = __float2half_rn(v.z);
    h[3] = __float2half_rn(v.w);
    char* base = reinterpret_cast<char*>(g_A);
    *reinterpret_cast<uint2*>(base + tile_off(bm, r, k4 * 4, nch)) =
        *reinterpret_cast<uint2*>(h);

    if (blockIdx.x == 0) {
        int j = threadIdx.x;
        int ntask = ktot - IC;
        if (j < ntask) {
            __half hv;
            if (j < NOUT) {
                int c = cols[j];
                hv = __float2half_rn(x[(size_t)t * IC + c]);
            } else {
                hv = __float2half_rn(0.f);
            }
            *reinterpret_cast<__half*>(base + tile_off(bm, r, IC + j, nch)) = hv;
        }
    }
}

// ---------------------------------------------------------------------------
// Kernel 4: fp16 GEMM. BM=BN=128, BK=64, 8 warps (2m x 4n of 64x32 tiles),
// 3-stage pipeline fed by cp.async.bulk + mbarrier, 2 CTAs/SM,
// ks-level register double-buffered fragments, epilogue scale+bias.
// ---------------------------------------------------------------------------
#define BM 128
#define BN 128
#define BK 64
#define NSTAGE 3
#define STAGE_BYTES  (2 * TILE_BYTES)               // A + B = 32 KB
#define GEMM_SMEM    (NSTAGE * STAGE_BYTES + 1024)  // ~97 KB -> 2 CTAs/SM

__global__ __launch_bounds__(256, 2)
void gemm_mma(const float* __restrict__ bias, float* __restrict__ C,
              int T, int OC, int ktot) {
    extern __shared__ char sm_raw[];
    uint32_t raw = smem_u32(sm_raw);
    uint32_t sbase = (raw + 1023u) & ~1023u;

    __shared__ uint64_t s_bar[NSTAGE];

    const int tid = threadIdx.x;
    const int lane = tid & 31, wid = tid >> 5;
    const int wm = (wid & 1) * 64;       // 2 warps in m
    const int wn = (wid >> 1) * 32;      // 4 warps in n
    const int nch = ktot >> 6;

    uint32_t bar[NSTAGE];
    #pragma unroll
    for (int s = 0; s < NSTAGE; s++) bar[s] = smem_u32(&s_bar[s]);

    if (tid == 0) {
        #pragma unroll
        for (int s = 0; s < NSTAGE; s++) MBAR_INIT(bar[s], 1);
        FENCE_ASYNC_SHARED();
    }
    __syncthreads();

    const char* Ag = reinterpret_cast<const char*>(g_A)
                     + (size_t)blockIdx.y * nch * TILE_BYTES;
    const char* Bg = reinterpret_cast<const char*>(g_B)
                     + (size_t)blockIdx.x * nch * TILE_BYTES;

    float acc[4][4][4];
    #pragma unroll
    for (int mi = 0; mi < 4; mi++)
        #pragma unroll
        for (int nb = 0; nb < 4; nb++)
            #pragma unroll
            for (int e = 0; e < 4; e++) acc[mi][nb][e] = 0.f;

    // Prologue: fill stages 0..NSTAGE-2.
    if (tid == 0) {
        #pragma unroll
        for (int s = 0; s < NSTAGE - 1; s++) {
            uint32_t st = sbase + (uint32_t)s * STAGE_BYTES;
            MBAR_EXPECT_TX(bar[s], 2 * TILE_BYTES);
            BULK_CP(st,              Ag + (size_t)s * TILE_BYTES, TILE_BYTES, bar[s]);
            BULK_CP(st + TILE_BYTES, Bg + (size_t)s * TILE_BYTES, TILE_BYTES, bar[s]);
        }
    }

    const int lrow = lane & 15;
    const int lkoff = (lane >> 4) * 16;
    const uint32_t arowoff = (uint32_t)((wm + lrow) * 128 + lkoff);
    const uint32_t browoff = (uint32_t)((wn + lrow) * 128 + lkoff);

    uint32_t afrag[2][4][4], bfrag[2][2][4];

    for (int ch = 0; ch < nch; ch++) {
        int s = ch % NSTAGE;
        MBAR_WAIT(bar[s], (ch / NSTAGE) & 1);
        __syncthreads();   // all threads done with stage being refilled below

        int pf = ch + NSTAGE - 1;
        if (tid == 0 && pf < nch) {
            int sp = pf % NSTAGE;
            uint32_t st = sbase + (uint32_t)sp * STAGE_BYTES;
            MBAR_EXPECT_TX(bar[sp], 2 * TILE_BYTES);
            BULK_CP(st,              Ag + (size_t)pf * TILE_BYTES, TILE_BYTES, bar[sp]);
            BULK_CP(st + TILE_BYTES, Bg + (size_t)pf * TILE_BYTES, TILE_BYTES, bar[sp]);
        }

        uint32_t st = sbase + (uint32_t)s * STAGE_BYTES;
        uint32_t ab = st, bb = st + TILE_BYTES;

        // Preload ks=0 fragments into buffer 0.
        #pragma unroll
        for (int ni = 0; ni < 2; ni++)
            ldsm4(bfrag[0][ni], bb + swz(browoff + (uint32_t)(ni * 2048)));
        #pragma unroll
        for (int mi = 0; mi < 4; mi++)
            ldsm4(afrag[0][mi], ab + swz(arowoff + (uint32_t)(mi * 2048)));

        #pragma unroll
        for (int ks = 0; ks < 4; ks++) {
            int cur = ks & 1;
            int nxt = cur ^ 1;
            if (ks < 3) {
                uint32_t ko = (uint32_t)((ks + 1) * 32);
                #pragma unroll
                for (int ni = 0; ni < 2; ni++)
                    ldsm4(bfrag[nxt][ni],
                          bb + swz(browoff + ko + (uint32_t)(ni * 2048)));
                #pragma unroll
                for (int mi = 0; mi < 4; mi++)
                    ldsm4(afrag[nxt][mi],
                          ab + swz(arowoff + ko + (uint32_t)(mi * 2048)));
            }
            #pragma unroll
            for (int mi = 0; mi < 4; mi++) {
                #pragma unroll
                for (int ni = 0; ni < 2; ni++) {
                    mma16816(acc[mi][2 * ni],     afrag[cur][mi],
                             bfrag[cur][ni][0], bfrag[cur][ni][2]);
                    mma16816(acc[mi][2 * ni + 1], afrag[cur][mi],
                             bfrag[cur][ni][1], bfrag[cur][ni][3]);
                }
            }
        }
    }

    // Epilogue: C = acc * s_eff[col] + bias[col]
    int colb = blockIdx.x * BN + wn + (lane & 3) * 2;
    int rowb = blockIdx.y * BM + wm + (lane >> 2);
    #pragma unroll
    for (int nb = 0; nb < 4; nb++) {
        int col = colb + nb * 8;
        float s0 = g_seff[col],     s1 = g_seff[col + 1];
        float b0 = bias[col],       b1 = bias[col + 1];
        #pragma unroll
        for (int mi = 0; mi < 4; mi++) {
            int row = rowb + mi * 16;
            float2 v0 = make_float2(acc[mi][nb][0] * s0 + b0,
                                    acc[mi][nb][1] * s1 + b1);
            float2 v1 = make_float2(acc[mi][nb][2] * s0 + b0,
                                    acc[mi][nb][3] * s1 + b1);
            *reinterpret_cast<float2*>(C + (size_t)row * OC + col)       = v0;
            *reinterpret_cast<float2*>(C + (size_t)(row + 8) * OC + col) = v1;
        }
    }
}

// ---------------------------------------------------------------------------
// Launch
// ---------------------------------------------------------------------------
extern "C" void kernel_launch(void* const* d_in, const int* in_sizes, int n_in,
                              void* d_out, int out_size) {
    const float* x    = (const float*)d_in[0];
    const float* w    = (const float*)d_in[1];
    const float* bias = (const float*)d_in[2];
    const float* ow   = (const float*)d_in[3];
    const int*   cols = (const int*)d_in[4];

    int OC   = in_sizes[2];
    int IC   = in_sizes[1] / OC;
    int T    = in_sizes[0] / IC;
    int NOUT = in_sizes[3] / OC;
    int ktot = (IC + NOUT + 63) & ~63;   // 4352

    float* out = (float*)d_out;

    // 1) row stats
    rowstats_kernel<<<OC, 256>>>(w, IC);

    // 2) B sign matrix (tiled layout) + fused outlier tail
    {
        dim3 grid(IC / 1024, OC);
        prepB_kernel<<<grid, 256>>>(w, ow, cols, IC, NOUT, ktot);
    }
    // 3) A fp16 (tiled layout) + fused gathered tail
    {
        dim3 grid(IC / 1024, T);
        prepA_kernel<<<grid, 256>>>(x, cols, IC, NOUT, ktot);
    }
    // 4) GEMM + scaled epilogue
    {
        static bool attr_set = false;
        if (!attr_set) {
            cudaFuncSetAttribute(gemm_mma,
                                 cudaFuncAttributeMaxDynamicSharedMemorySize,
                                 GEMM_SMEM);
            attr_set = true;
        }
        dim3 grid(OC / BN, T / BM);
        gemm_mma<<<grid, 256, GEMM_SMEM>>>(bias, out, T, OC, ktot);
    }
}